// round 1
// baseline (speedup 1.0000x reference)
#include <cuda_runtime.h>
#include <cuda_bf16.h>

// Problem constants
#define NTOK 399          // n = N_TOKENS - 1
#define DIM  1024
#define NLAB 112

// Scratch for u = fp @ W^T  (399 x 1024 fp32)
__device__ float g_u[NTOK * DIM];

// Accurate-enough fast tanh: tanh(x) = sign(x) * (1 - e)/(1 + e), e = exp(-2|x|)
// EX2 + RCP (MUFU) + a few FMA; rel err ~1e-6 (vs tanh.approx's 4.9e-4 abs).
__device__ __forceinline__ float tanh_fast(float x) {
    float ax = fabsf(x);
    float e  = __expf(-2.0f * ax);
    float r  = __fdividef(1.0f - e, 1.0f + e);
    return copysignf(r, x);
}

// ---------------------------------------------------------------------------
// Stage 1: u[j,r] = sum_d fp[j,d] * W[r,d]
//   fp[j,d] = x[j,d]        (d < 512)
//           = -x[j+1,d]     (d >= 512)
// Tiled 64x64, K-chunks of 16, 256 threads, 4x4 per thread.
// ---------------------------------------------------------------------------
__global__ void stage1_u_gemm(const float* __restrict__ x,
                              const float* __restrict__ W) {
    __shared__ float As[16][68];   // [k][j], stride 68 keeps 16B alignment
    __shared__ float Bs[16][68];   // [k][r]

    const int j0 = blockIdx.y * 64;
    const int r0 = blockIdx.x * 64;
    const int t  = threadIdx.x;          // 0..255
    const int ty = t >> 4;               // 0..15 (j groups)
    const int tx = t & 15;               // 0..15 (r groups)

    float acc[4][4];
#pragma unroll
    for (int e = 0; e < 4; e++)
#pragma unroll
        for (int f = 0; f < 4; f++) acc[e][f] = 0.0f;

    for (int k0 = 0; k0 < DIM; k0 += 16) {
        // Load fp tile (64 j x 16 k) as float4 per thread
        {
            const int jj = t >> 2;
            const int kv = (t & 3) << 2;
            const int j  = j0 + jj;
            const int k  = k0 + kv;
            float4 v = make_float4(0.f, 0.f, 0.f, 0.f);
            if (j < NTOK) {
                if (k < 512) {
                    v = *reinterpret_cast<const float4*>(&x[(size_t)j * DIM + k]);
                } else {
                    float4 w = *reinterpret_cast<const float4*>(&x[(size_t)(j + 1) * DIM + k]);
                    v = make_float4(-w.x, -w.y, -w.z, -w.w);
                }
            }
            As[kv + 0][jj] = v.x; As[kv + 1][jj] = v.y;
            As[kv + 2][jj] = v.z; As[kv + 3][jj] = v.w;
        }
        // Load W tile (64 r x 16 k)
        {
            const int rr = t >> 2;
            const int kv = (t & 3) << 2;
            float4 v = *reinterpret_cast<const float4*>(&W[(size_t)(r0 + rr) * DIM + k0 + kv]);
            Bs[kv + 0][rr] = v.x; Bs[kv + 1][rr] = v.y;
            Bs[kv + 2][rr] = v.z; Bs[kv + 3][rr] = v.w;
        }
        __syncthreads();

#pragma unroll
        for (int kk = 0; kk < 16; kk++) {
            float4 a4 = *reinterpret_cast<const float4*>(&As[kk][ty << 2]);
            float4 b4 = *reinterpret_cast<const float4*>(&Bs[kk][tx << 2]);
            float a[4] = {a4.x, a4.y, a4.z, a4.w};
            float b[4] = {b4.x, b4.y, b4.z, b4.w};
#pragma unroll
            for (int e = 0; e < 4; e++)
#pragma unroll
                for (int f = 0; f < 4; f++)
                    acc[e][f] = fmaf(a[e], b[f], acc[e][f]);
        }
        __syncthreads();
    }

#pragma unroll
    for (int e = 0; e < 4; e++) {
        const int j = j0 + (ty << 2) + e;
        if (j < NTOK) {
#pragma unroll
            for (int f = 0; f < 4; f++)
                g_u[(size_t)j * DIM + r0 + (tx << 2) + f] = acc[e][f];
        }
    }
}

// ---------------------------------------------------------------------------
// Stage 2: out[i,j,l] = sum_r tanh(u[j,r] - u[i,r] + b[r]) * P[r,l] + ob[l]
// Grid: (ceil(399/64)=7, 399).  Each CTA: fixed i, 64 j's, all 112 l's.
// K-chunks of 32. 256 threads, each computes 4 j x 7 l.
// ---------------------------------------------------------------------------
__global__ void stage2_out_gemm(const float* __restrict__ b,
                                const float* __restrict__ P,
                                const float* __restrict__ ob,
                                float* __restrict__ out) {
    __shared__ float aS[32][68];    // tanh tile [k][j]
    __shared__ float pS[32][112];   // P tile    [k][l]

    const int i  = blockIdx.y;
    const int j0 = blockIdx.x * 64;
    const int t  = threadIdx.x;     // 0..255
    const int ty = t >> 4;          // j group (x4)
    const int tx = t & 15;          // l group (strided x7)

    float acc[4][7];
#pragma unroll
    for (int e = 0; e < 4; e++)
#pragma unroll
        for (int q = 0; q < 7; q++) acc[e][q] = 0.0f;

    for (int k0 = 0; k0 < DIM; k0 += 32) {
        // Build tanh tile: 64 j x 32 k = 512 float4 loads -> 2 per thread
#pragma unroll
        for (int rep = 0; rep < 2; rep++) {
            const int idx = t + rep * 256;        // 0..511
            const int jj  = idx >> 3;             // 0..63
            const int kv  = (idx & 7) << 2;       // 0,4,...,28
            const int j   = j0 + jj;
            float4 uj = make_float4(0.f, 0.f, 0.f, 0.f);
            if (j < NTOK)
                uj = *reinterpret_cast<const float4*>(&g_u[(size_t)j * DIM + k0 + kv]);
            float4 ui = *reinterpret_cast<const float4*>(&g_u[(size_t)i * DIM + k0 + kv]);
            float4 bv = *reinterpret_cast<const float4*>(&b[k0 + kv]);
            aS[kv + 0][jj] = tanh_fast(uj.x - ui.x + bv.x);
            aS[kv + 1][jj] = tanh_fast(uj.y - ui.y + bv.y);
            aS[kv + 2][jj] = tanh_fast(uj.z - ui.z + bv.z);
            aS[kv + 3][jj] = tanh_fast(uj.w - ui.w + bv.w);
        }
        // P tile: 32 x 112 = 3584 floats -> 14 scalars per thread (coalesced)
#pragma unroll
        for (int rep = 0; rep < 14; rep++) {
            const int idx = t + rep * 256;        // 0..3583
            const int kk  = idx / 112;
            const int l   = idx % 112;
            pS[kk][l] = P[(size_t)(k0 + kk) * NLAB + l];
        }
        __syncthreads();

#pragma unroll
        for (int kk = 0; kk < 32; kk++) {
            float4 a4 = *reinterpret_cast<const float4*>(&aS[kk][ty << 2]);
            float a[4] = {a4.x, a4.y, a4.z, a4.w};
            float p[7];
#pragma unroll
            for (int q = 0; q < 7; q++) p[q] = pS[kk][tx + 16 * q];
#pragma unroll
            for (int e = 0; e < 4; e++)
#pragma unroll
                for (int q = 0; q < 7; q++)
                    acc[e][q] = fmaf(a[e], p[q], acc[e][q]);
        }
        __syncthreads();
    }

#pragma unroll
    for (int e = 0; e < 4; e++) {
        const int j = j0 + (ty << 2) + e;
        if (j < NTOK) {
            const size_t base = ((size_t)i * NTOK + j) * NLAB;
#pragma unroll
            for (int q = 0; q < 7; q++) {
                const int l = tx + 16 * q;
                out[base + l] = acc[e][q] + ob[l];
            }
        }
    }
}

// ---------------------------------------------------------------------------
// Launch: inputs per metadata order: x, W, b, P, out_bias
// ---------------------------------------------------------------------------
extern "C" void kernel_launch(void* const* d_in, const int* in_sizes, int n_in,
                              void* d_out, int out_size) {
    const float* x  = (const float*)d_in[0];   // (400, 1024)
    const float* W  = (const float*)d_in[1];   // (1024, 1024)
    const float* b  = (const float*)d_in[2];   // (1024,)
    const float* P  = (const float*)d_in[3];   // (1024, 112)
    const float* ob = (const float*)d_in[4];   // (1, 112)
    float* out = (float*)d_out;                // (399, 399, 112)

    dim3 g1(DIM / 64, (NTOK + 63) / 64);       // (16, 7)
    stage1_u_gemm<<<g1, 256>>>(x, W);

    dim3 g2((NTOK + 63) / 64, NTOK);           // (7, 399)
    stage2_out_gemm<<<g2, 256>>>(b, P, ob, out);
}

// round 3
// speedup vs baseline: 2.5209x; 2.5209x over previous
#include <cuda_runtime.h>
#include <cuda_bf16.h>
#include <cstdint>

#define NTOK 399
#define DIM  1024
#define NLAB 112
#define JPAD 512
#define NCH  16          // K chunks
#define CHK  64          // K per chunk

// ---------------- device scratch (zero-initialized) ----------------
__device__ float g_u[NTOK * DIM];                 // u = fp @ W^T
__device__ float g_aexp[NCH * JPAD * CHK];        // [c][j][kk] = exp(-2(u_j+b)); pad rows 0
__device__ float g_cexp[(NTOK + 1) * DIM];        // [i][k] = exp(2 u_i)
__device__ float g_Btf[DIM * NLAB];               // tf32-rounded P [k][l]

__device__ __forceinline__ float to_tf32(float x) {
    float r;
    asm("cvt.rna.tf32.f32 %0, %1;" : "=f"(r) : "f"(x));
    return r;
}

__device__ __forceinline__ void mma_tf32(float d[4], const uint32_t a[4], const uint32_t b[2]) {
    asm volatile(
        "mma.sync.aligned.m16n8k8.row.col.f32.tf32.tf32.f32 "
        "{%0,%1,%2,%3},{%4,%5,%6,%7},{%8,%9},{%0,%1,%2,%3};"
        : "+f"(d[0]), "+f"(d[1]), "+f"(d[2]), "+f"(d[3])
        : "r"(a[0]), "r"(a[1]), "r"(a[2]), "r"(a[3]), "r"(b[0]), "r"(b[1]));
}

// ---------------------------------------------------------------------------
// Stage 1: u[j,r] = sum_d fp[j,d] * W[r,d]   (fp32 SIMT, small)
// ---------------------------------------------------------------------------
__global__ void stage1_u_gemm(const float* __restrict__ x, const float* __restrict__ W) {
    __shared__ float As[16][68];
    __shared__ float Bs[16][68];
    const int j0 = blockIdx.y * 64, r0 = blockIdx.x * 64;
    const int t = threadIdx.x, ty = t >> 4, tx = t & 15;
    float acc[4][4];
#pragma unroll
    for (int e = 0; e < 4; e++)
#pragma unroll
        for (int f = 0; f < 4; f++) acc[e][f] = 0.0f;
    for (int k0 = 0; k0 < DIM; k0 += 16) {
        {
            const int jj = t >> 2, kv = (t & 3) << 2;
            const int j = j0 + jj, k = k0 + kv;
            float4 v = make_float4(0.f, 0.f, 0.f, 0.f);
            if (j < NTOK) {
                if (k < 512) v = *reinterpret_cast<const float4*>(&x[(size_t)j * DIM + k]);
                else { float4 w = *reinterpret_cast<const float4*>(&x[(size_t)(j + 1) * DIM + k]);
                       v = make_float4(-w.x, -w.y, -w.z, -w.w); }
            }
            As[kv + 0][jj] = v.x; As[kv + 1][jj] = v.y; As[kv + 2][jj] = v.z; As[kv + 3][jj] = v.w;
        }
        {
            const int rr = t >> 2, kv = (t & 3) << 2;
            float4 v = *reinterpret_cast<const float4*>(&W[(size_t)(r0 + rr) * DIM + k0 + kv]);
            Bs[kv + 0][rr] = v.x; Bs[kv + 1][rr] = v.y; Bs[kv + 2][rr] = v.z; Bs[kv + 3][rr] = v.w;
        }
        __syncthreads();
#pragma unroll
        for (int kk = 0; kk < 16; kk++) {
            float4 a4 = *reinterpret_cast<const float4*>(&As[kk][ty << 2]);
            float4 b4 = *reinterpret_cast<const float4*>(&Bs[kk][tx << 2]);
            float a[4] = {a4.x, a4.y, a4.z, a4.w}, b[4] = {b4.x, b4.y, b4.z, b4.w};
#pragma unroll
            for (int e = 0; e < 4; e++)
#pragma unroll
                for (int f = 0; f < 4; f++) acc[e][f] = fmaf(a[e], b[f], acc[e][f]);
        }
        __syncthreads();
    }
#pragma unroll
    for (int e = 0; e < 4; e++) {
        const int j = j0 + (ty << 2) + e;
        if (j < NTOK)
#pragma unroll
            for (int f = 0; f < 4; f++)
                g_u[(size_t)j * DIM + r0 + (tx << 2) + f] = acc[e][f];
    }
}

// ---------------------------------------------------------------------------
// Prep: exp tables
// ---------------------------------------------------------------------------
__global__ void prep_exp(const float* __restrict__ b) {
    const int j = blockIdx.x;
    for (int k = threadIdx.x; k < DIM; k += blockDim.x) {
        float u = g_u[j * DIM + k];
        g_cexp[j * DIM + k] = __expf(2.0f * u);
        g_aexp[((k >> 6) * JPAD + j) * CHK + (k & 63)] = __expf(-2.0f * (u + b[k]));
    }
}

// Prep: P rounded to tf32
__global__ void prep_B(const float* __restrict__ P) {
    const int idx = blockIdx.x * blockDim.x + threadIdx.x;
    if (idx < DIM * NLAB) g_Btf[idx] = to_tf32(P[idx]);
}

// ---------------------------------------------------------------------------
// Stage 2: per-CTA fixed i, 128 j's, all 112 l's.  tf32 mma.sync.
// smem floats: obS[112]@0, cS[1024]@128, aS[128][68]@1152, bS[64][120]@9856
// ---------------------------------------------------------------------------
#define S_OB 0
#define S_CS 128
#define S_AS 1152
#define S_BS 9856
#define S_TOT 17536              // floats -> 70144 bytes
#define AST 68                   // aS row stride (floats)
#define BST 120                  // bS row stride (floats)

__global__ void __launch_bounds__(256)
stage2_mma(const float* __restrict__ ob, float* __restrict__ out) {
    extern __shared__ float sm[];
    const int t = threadIdx.x, lane = t & 31, wid = t >> 5;
    const int i = blockIdx.y, j0 = blockIdx.x * 128;
    const int warpM = wid & 3, warpN = wid >> 2;        // 4 x 2 warps
    const int m0 = warpM * 32, n0 = warpN * 56;
    const int g = lane >> 2, tq = lane & 3;

    // bias + cexp row i into smem
    if (t < NLAB) sm[S_OB + t] = ob[t];
    {
        float4* dst = reinterpret_cast<float4*>(sm + S_CS);
        const float4* src = reinterpret_cast<const float4*>(&g_cexp[(size_t)i * DIM]);
        for (int q = t; q < 256; q += 256) dst[q] = src[q];
    }

    float acc[2][7][4];
#pragma unroll
    for (int m = 0; m < 2; m++)
#pragma unroll
        for (int q = 0; q < 7; q++)
#pragma unroll
            for (int e = 0; e < 4; e++) acc[m][q][e] = 0.0f;

    for (int c = 0; c < NCH; ++c) {
        __syncthreads();   // previous chunk's mma done reading aS/bS (also covers cS init on c==0)
        // ---- build A tile: tanh((aexp*cexp)) as tf32, 128 x 64 ----
        {
            const float* asrc = g_aexp + ((size_t)c * JPAD + j0) * CHK;
            const float* cch = sm + S_CS + c * CHK;
#pragma unroll
            for (int r = 0; r < 8; ++r) {
                const int idx = t + 256 * r;           // 0..2047
                const int jj = idx >> 4, kv = (idx & 15) << 2;
                float4 a = *reinterpret_cast<const float4*>(asrc + jj * CHK + kv);
                float4 cc = *reinterpret_cast<const float4*>(cch + kv);
                float e0 = a.x * cc.x, e1 = a.y * cc.y, e2 = a.z * cc.z, e3 = a.w * cc.w;
                float4 o;
                o.x = to_tf32(__fdividef(1.0f - e0, 1.0f + e0));
                o.y = to_tf32(__fdividef(1.0f - e1, 1.0f + e1));
                o.z = to_tf32(__fdividef(1.0f - e2, 1.0f + e2));
                o.w = to_tf32(__fdividef(1.0f - e3, 1.0f + e3));
                *reinterpret_cast<float4*>(sm + S_AS + jj * AST + kv) = o;
            }
        }
        // ---- stage B tile: 64 x 112 (stride 120) ----
        {
            const float* bsrc = g_Btf + (size_t)c * CHK * NLAB;
#pragma unroll
            for (int r = 0; r < 7; ++r) {
                const int idx = t + 256 * r;           // 0..1791
                const int k = idx / 28, w = (idx % 28) << 2;
                *reinterpret_cast<float4*>(sm + S_BS + k * BST + w) =
                    *reinterpret_cast<const float4*>(bsrc + k * NLAB + w);
            }
        }
        __syncthreads();
        // ---- 8 k-steps of m16n8k8 ----
#pragma unroll
        for (int ks = 0; ks < 8; ++ks) {
            const int kc = ks * 8 + tq;
            uint32_t afr[2][4];
            const uint32_t* aSu = reinterpret_cast<const uint32_t*>(sm + S_AS);
#pragma unroll
            for (int m = 0; m < 2; ++m) {
                const int rb = m0 + m * 16 + g;
                afr[m][0] = aSu[rb * AST + kc];
                afr[m][1] = aSu[(rb + 8) * AST + kc];
                afr[m][2] = aSu[rb * AST + kc + 4];
                afr[m][3] = aSu[(rb + 8) * AST + kc + 4];
            }
            const uint32_t* bSu = reinterpret_cast<const uint32_t*>(sm + S_BS);
#pragma unroll
            for (int q = 0; q < 7; ++q) {
                const int col = n0 + q * 8 + g;
                uint32_t bfr[2];
                bfr[0] = bSu[(ks * 8 + tq) * BST + col];
                bfr[1] = bSu[(ks * 8 + tq + 4) * BST + col];
                mma_tf32(acc[0][q], afr[0], bfr);
                mma_tf32(acc[1][q], afr[1], bfr);
            }
        }
    }

    // ---- epilogue ----
#pragma unroll
    for (int m = 0; m < 2; ++m) {
        const int ja = j0 + m0 + m * 16 + g;
        const int jb = ja + 8;
#pragma unroll
        for (int q = 0; q < 7; ++q) {
            const int l = n0 + q * 8 + tq * 2;
            const float b0 = sm[S_OB + l], b1 = sm[S_OB + l + 1];
            if (ja < NTOK) {
                float2 v = make_float2(acc[m][q][0] + b0, acc[m][q][1] + b1);
                *reinterpret_cast<float2*>(out + ((size_t)i * NTOK + ja) * NLAB + l) = v;
            }
            if (jb < NTOK) {
                float2 v = make_float2(acc[m][q][2] + b0, acc[m][q][3] + b1);
                *reinterpret_cast<float2*>(out + ((size_t)i * NTOK + jb) * NLAB + l) = v;
            }
        }
    }
}

// ---------------------------------------------------------------------------
extern "C" void kernel_launch(void* const* d_in, const int* in_sizes, int n_in,
                              void* d_out, int out_size) {
    (void)in_sizes; (void)n_in; (void)out_size;
    const float* x  = (const float*)d_in[0];
    const float* W  = (const float*)d_in[1];
    const float* b  = (const float*)d_in[2];
    const float* P  = (const float*)d_in[3];
    const float* ob = (const float*)d_in[4];
    float* out = (float*)d_out;

    cudaFuncSetAttribute(stage2_mma, cudaFuncAttributeMaxDynamicSharedMemorySize, S_TOT * 4);

    dim3 g1(DIM / 64, (NTOK + 63) / 64);
    stage1_u_gemm<<<g1, 256>>>(x, W);
    prep_exp<<<NTOK, 256>>>(b);
    prep_B<<<(DIM * NLAB + 255) / 256, 256>>>(P);
    dim3 g2(4, NTOK);                       // (j-tiles, i)
    stage2_mma<<<g2, 256, S_TOT * 4>>>(ob, out);
}

// round 4
// speedup vs baseline: 3.2131x; 1.2746x over previous
#include <cuda_runtime.h>
#include <cuda_bf16.h>
#include <cstdint>

#define NTOK 399
#define DIM  1024
#define NLAB 112
#define JPAD 512
#define NCH  16
#define CHK  64

// ---------------- device scratch (zero-initialized .bss) ----------------
// aexp in mma-fragment-permuted order:
// [(c*4+jt)*8192 + (mb*8+kb)*128 + (g*4+tq)*4 + rhi + 2*khi]
__device__ float g_aexp[NCH * JPAD * CHK];
__device__ float g_cexp[(NTOK + 1) * DIM];
// P (tf32) permuted: [c*7168 + ((kp*112+l)*4+tq)*4 + (ks&1)*2 + khi]
__device__ float g_Bp[DIM * NLAB];

__device__ __forceinline__ float to_tf32(float x) {
    float r;
    asm("cvt.rna.tf32.f32 %0, %1;" : "=f"(r) : "f"(x));
    return r;
}
__device__ __forceinline__ void mma_tf32(float d[4], const uint32_t a[4], uint32_t b0, uint32_t b1) {
    asm volatile(
        "mma.sync.aligned.m16n8k8.row.col.f32.tf32.tf32.f32 "
        "{%0,%1,%2,%3},{%4,%5,%6,%7},{%8,%9},{%0,%1,%2,%3};"
        : "+f"(d[0]), "+f"(d[1]), "+f"(d[2]), "+f"(d[3])
        : "r"(a[0]), "r"(a[1]), "r"(a[2]), "r"(a[3]), "r"(b0), "r"(b1));
}
__device__ __forceinline__ uint32_t smem_u32(const void* p) {
    uint32_t a;
    asm("{ .reg .u64 t; cvta.to.shared.u64 t, %1; cvt.u32.u64 %0, t; }" : "=r"(a) : "l"(p));
    return a;
}
__device__ __forceinline__ void cp16(uint32_t dst, const void* src) {
    asm volatile("cp.async.cg.shared.global [%0], [%1], 16;" :: "r"(dst), "l"(src));
}
#define CP_COMMIT() asm volatile("cp.async.commit_group;" ::: "memory")
#define CP_WAIT(n)  asm volatile("cp.async.wait_group %0;" :: "n"(n) : "memory")

// ---------------------------------------------------------------------------
// Stage 1: u = fp @ W^T, epilogue fused with exp tables (permuted aexp)
// ---------------------------------------------------------------------------
__global__ void stage1_u_gemm(const float* __restrict__ x, const float* __restrict__ W,
                              const float* __restrict__ bias) {
    __shared__ float As[16][68];
    __shared__ float Bs[16][68];
    const int j0 = blockIdx.y * 64, r0 = blockIdx.x * 64;
    const int t = threadIdx.x, ty = t >> 4, tx = t & 15;
    float acc[4][4];
#pragma unroll
    for (int e = 0; e < 4; e++)
#pragma unroll
        for (int f = 0; f < 4; f++) acc[e][f] = 0.0f;
    for (int k0 = 0; k0 < DIM; k0 += 16) {
        {
            const int jj = t >> 2, kv = (t & 3) << 2;
            const int j = j0 + jj, k = k0 + kv;
            float4 v = make_float4(0.f, 0.f, 0.f, 0.f);
            if (j < NTOK) {
                if (k < 512) v = *reinterpret_cast<const float4*>(&x[(size_t)j * DIM + k]);
                else { float4 w = *reinterpret_cast<const float4*>(&x[(size_t)(j + 1) * DIM + k]);
                       v = make_float4(-w.x, -w.y, -w.z, -w.w); }
            }
            As[kv + 0][jj] = v.x; As[kv + 1][jj] = v.y; As[kv + 2][jj] = v.z; As[kv + 3][jj] = v.w;
        }
        {
            const int rr = t >> 2, kv = (t & 3) << 2;
            float4 v = *reinterpret_cast<const float4*>(&W[(size_t)(r0 + rr) * DIM + k0 + kv]);
            Bs[kv + 0][rr] = v.x; Bs[kv + 1][rr] = v.y; Bs[kv + 2][rr] = v.z; Bs[kv + 3][rr] = v.w;
        }
        __syncthreads();
#pragma unroll
        for (int kk = 0; kk < 16; kk++) {
            float4 a4 = *reinterpret_cast<const float4*>(&As[kk][ty << 2]);
            float4 b4 = *reinterpret_cast<const float4*>(&Bs[kk][tx << 2]);
            float a[4] = {a4.x, a4.y, a4.z, a4.w}, b[4] = {b4.x, b4.y, b4.z, b4.w};
#pragma unroll
            for (int e = 0; e < 4; e++)
#pragma unroll
                for (int f = 0; f < 4; f++) acc[e][f] = fmaf(a[e], b[f], acc[e][f]);
        }
        __syncthreads();
    }
    // fused epilogue: exps (no g_u)
    float bb[4];
#pragma unroll
    for (int f = 0; f < 4; f++) bb[f] = bias[r0 + (tx << 2) + f];
#pragma unroll
    for (int e = 0; e < 4; e++) {
        const int j = j0 + (ty << 2) + e;
        if (j >= NTOK) continue;
        const int jt = j >> 7, jj = j & 127;
        const int mb = jj >> 4, rr = jj & 15, rhi = rr >> 3, g = rr & 7;
#pragma unroll
        for (int f = 0; f < 4; f++) {
            const int r = r0 + (tx << 2) + f;
            const float u = acc[e][f];
            g_cexp[(size_t)j * DIM + r] = __expf(2.0f * u);
            const int c = r >> 6, kk = r & 63;
            const int kb = kk >> 3, kq = kk & 7, khi = kq >> 2, tq = kq & 3;
            const int off = (c * 4 + jt) * 8192 + (mb * 8 + kb) * 128 + (g * 4 + tq) * 4 + rhi + 2 * khi;
            g_aexp[off] = __expf(-2.0f * (u + bb[f]));
        }
    }
}

// ---------------------------------------------------------------------------
// Prep: P -> tf32, B-fragment-permuted
// ---------------------------------------------------------------------------
__global__ void prep_B(const float* __restrict__ P) {
    const int idx = blockIdx.x * blockDim.x + threadIdx.x;
    if (idx >= DIM * NLAB) return;
    const int k = idx / NLAB, l = idx % NLAB;
    const int c = k >> 6, kk = k & 63;
    const int ks = kk >> 3, kq = kk & 7, khi = kq >> 2, tq = kq & 3;
    const int kp = ks >> 1, kslow = ks & 1;
    const int off = c * 7168 + ((kp * 112 + l) * 4 + tq) * 4 + kslow * 2 + khi;
    g_Bp[off] = to_tf32(P[idx]);
}

// ---------------------------------------------------------------------------
// Stage 2: per-CTA fixed i, 128 j's. Permuted LDS.128 fragments + cp.async B.
// smem floats: ob[112]@0, cS[1024]@128, A[8192]@1152, B0[7168]@9344, B1@16512
// ---------------------------------------------------------------------------
#define S_OB 0
#define S_CS 128
#define S_A  1152
#define S_B0 9344
#define S_B1 16512
#define S_TOT 23680   // floats -> 94720 bytes

__global__ void __launch_bounds__(256, 2)
stage2_mma(const float* __restrict__ ob, float* __restrict__ out) {
    extern __shared__ float sm[];
    const uint32_t sb = smem_u32(sm);
    const int t = threadIdx.x, lane = t & 31, wid = t >> 5;
    const int i = blockIdx.y, jt = blockIdx.x, j0 = jt * 128;
    const int warpM = wid & 3, warpN = wid >> 2;
    const int m0 = warpM * 32, n0 = warpN * 56;
    const int g = lane >> 2, tq = lane & 3;

    if (t < NLAB) sm[S_OB + t] = ob[t];
    {
        float4* dst = reinterpret_cast<float4*>(sm + S_CS);
        const float4* src = reinterpret_cast<const float4*>(&g_cexp[(size_t)i * DIM]);
        dst[t] = src[t];
    }
    // prologue: stage B[0]
    {
        const float4* src = reinterpret_cast<const float4*>(g_Bp);
#pragma unroll
        for (int r = 0; r < 7; ++r) {
            const int q = t + 256 * r;
            cp16(sb + (S_B0 + q * 4) * 4, src + q);
        }
        CP_COMMIT();
    }

    float acc[2][7][4];
#pragma unroll
    for (int m = 0; m < 2; m++)
#pragma unroll
        for (int q = 0; q < 7; q++)
#pragma unroll
            for (int e = 0; e < 4; e++) acc[m][q][e] = 0.0f;

    const float4* aperm = reinterpret_cast<const float4*>(g_aexp) + (size_t)jt * 2048;

    for (int c = 0; c < NCH; ++c) {
        __syncthreads();   // prev chunk mma done (A and B[(c-1)&1] free); covers cS/ob on c==0
        // prefetch B[c+1] into buffer (c+1)&1
        if (c + 1 < NCH) {
            const float4* src = reinterpret_cast<const float4*>(g_Bp + (size_t)(c + 1) * 7168);
            const int bbase = ((c + 1) & 1) ? S_B1 : S_B0;
#pragma unroll
            for (int r = 0; r < 7; ++r) {
                const int q = t + 256 * r;
                cp16(sb + (bbase + q * 4) * 4, src + q);
            }
            CP_COMMIT();
        }
        // build A tile (coalesced permuted loads -> tanh -> permuted smem)
        {
            const float4* asrc = aperm + (size_t)c * 8192;  // (c*4+jt)*2048 float4s
            const float* cch = sm + S_CS + c * CHK;
#pragma unroll
            for (int r = 0; r < 8; ++r) {
                const int idx4 = t + 256 * r;
                float4 a = asrc[idx4];
                const int kb_ = (idx4 >> 5) & 7, tq_ = idx4 & 3;
                const float c0 = cch[kb_ * 8 + tq_];
                const float c1 = cch[kb_ * 8 + tq_ + 4];
                float e0 = a.x * c0, e1 = a.y * c0, e2 = a.z * c1, e3 = a.w * c1;
                float4 o;
                o.x = to_tf32(__fdividef(1.0f - e0, 1.0f + e0));
                o.y = to_tf32(__fdividef(1.0f - e1, 1.0f + e1));
                o.z = to_tf32(__fdividef(1.0f - e2, 1.0f + e2));
                o.w = to_tf32(__fdividef(1.0f - e3, 1.0f + e3));
                *reinterpret_cast<float4*>(sm + S_A + idx4 * 4) = o;
            }
        }
        if (c + 1 < NCH) { CP_WAIT(1); } else { CP_WAIT(0); }
        __syncthreads();
        // mma: 4 k-pairs x 2 k-steps
        const float* bbuf = sm + ((c & 1) ? S_B1 : S_B0);
#pragma unroll
        for (int kp = 0; kp < 4; ++kp) {
            uint4 bfr[7];
#pragma unroll
            for (int q = 0; q < 7; ++q)
                bfr[q] = *reinterpret_cast<const uint4*>(bbuf + ((kp * 112 + n0 + q * 8 + g) * 4 + tq) * 4);
#pragma unroll
            for (int ks2 = 0; ks2 < 2; ++ks2) {
                const int kb = kp * 2 + ks2;
                uint32_t afr[2][4];
#pragma unroll
                for (int m = 0; m < 2; ++m) {
                    const int mb = warpM * 2 + m;
                    uint4 v = *reinterpret_cast<const uint4*>(sm + S_A + ((mb * 8 + kb) * 128 + lane * 4));
                    afr[m][0] = v.x; afr[m][1] = v.y; afr[m][2] = v.z; afr[m][3] = v.w;
                }
#pragma unroll
                for (int q = 0; q < 7; ++q) {
                    const uint32_t b0 = ks2 ? bfr[q].z : bfr[q].x;
                    const uint32_t b1 = ks2 ? bfr[q].w : bfr[q].y;
                    mma_tf32(acc[0][q], afr[0], b0, b1);
                    mma_tf32(acc[1][q], afr[1], b0, b1);
                }
            }
        }
    }

    // epilogue
#pragma unroll
    for (int m = 0; m < 2; ++m) {
        const int ja = j0 + m0 + m * 16 + g;
        const int jb = ja + 8;
#pragma unroll
        for (int q = 0; q < 7; ++q) {
            const int l = n0 + q * 8 + tq * 2;
            const float b0 = sm[S_OB + l], b1 = sm[S_OB + l + 1];
            if (ja < NTOK) {
                float2 v = make_float2(acc[m][q][0] + b0, acc[m][q][1] + b1);
                *reinterpret_cast<float2*>(out + ((size_t)i * NTOK + ja) * NLAB + l) = v;
            }
            if (jb < NTOK) {
                float2 v = make_float2(acc[m][q][2] + b0, acc[m][q][3] + b1);
                *reinterpret_cast<float2*>(out + ((size_t)i * NTOK + jb) * NLAB + l) = v;
            }
        }
    }
}

// ---------------------------------------------------------------------------
extern "C" void kernel_launch(void* const* d_in, const int* in_sizes, int n_in,
                              void* d_out, int out_size) {
    (void)in_sizes; (void)n_in; (void)out_size;
    const float* x  = (const float*)d_in[0];
    const float* W  = (const float*)d_in[1];
    const float* b  = (const float*)d_in[2];
    const float* P  = (const float*)d_in[3];
    const float* ob = (const float*)d_in[4];
    float* out = (float*)d_out;

    cudaFuncSetAttribute(stage2_mma, cudaFuncAttributeMaxDynamicSharedMemorySize, S_TOT * 4);

    dim3 g1(DIM / 64, (NTOK + 63) / 64);
    stage1_u_gemm<<<g1, 256>>>(x, W, b);
    prep_B<<<(DIM * NLAB + 255) / 256, 256>>>(P);
    dim3 g2(4, NTOK);
    stage2_mma<<<g2, 256, S_TOT * 4>>>(ob, out);
}